// round 17
// baseline (speedup 1.0000x reference)
#include <cuda_runtime.h>
#include <cuda_bf16.h>
#include <cuda_fp16.h>
#include <stdint.h>

// DeepAR forward, tensor-core mma.sync m16n8k16 bf16, persistent 296x256.
// R15/R16: fully-overlapped 3-phase rotation. Pre-activations round-trip
// through thread-private fp16 smem scratch (no barrier needed), so each MUFU
// cell phase runs interleaved with an independent MMA stream:
//   phase1 : MMA0(t)=Whh0@h0(t-1)+x(t)   || cellL1(t-1)   ; pack pre0 ; bar1
//   phase2a: MMA1b  =Whh1@h1(t-1)        || cellL0(t)     ; x-stage; head; bar2
//   phase2b: MMA1a +=Wih1@h0(t)          -> pack pre1     ; (no barrier)
// Gate-permuted A rows (cell in-register), x folded into MMA0 (R14 machinery).
// (R16 resubmission: R15 bench was lost to a container infra failure.)

#define TPB 256
#define SEQ 56
#define NCTA 296
#define NSTEP 383
#define NSEQ_TOT 16384
#define PW0 88
#define PW1 72
#define PH0 88
#define PH1 72

// smem byte offsets
#define OB_W0   0               // [256][PW0] bf16 = 45056
#define OB_WI1  45056           // [256][PW1] bf16 = 36864
#define OB_WH1  81920           // 36864
#define OB_HT0  118784          // 2 x [64][PH0] bf16 (11264 each)
#define HT0_SZ  11264
#define OB_HT1  141312          // 2 x [64][PH1] bf16 (9216 each)
#define HT1_SZ  9216
#define OB_H1F  159744          // 2 x [56][66] f32 (14784 each)
#define H1F_SZ  14784
#define OB_SC   189312          // scratch [256][29] u32 = 29696 (thread-private)
#define OB_HW   219008          // head_W 128 f
#define OB_HB   219520          // head_b 2 f
#define SM_BYTES 219648

static __device__ __forceinline__ uint32_t s2u(const void* p) {
    uint32_t a;
    asm("{\n.reg .u64 t;\ncvta.to.shared.u64 t, %1;\ncvt.u32.u64 %0, t;\n}"
        : "=r"(a) : "l"(p));
    return a;
}
static __device__ __forceinline__ float tanh_(float x) {
    float r; asm("tanh.approx.f32 %0, %1;" : "=f"(r) : "f"(x)); return r;
}
static __device__ __forceinline__ float sigm_(float x) {
    return fmaf(0.5f, tanh_(0.5f * x), 0.5f);
}

#define MMA(dd, aa, b0, b1)                                                   \
    asm volatile(                                                             \
        "mma.sync.aligned.m16n8k16.row.col.f32.bf16.bf16.f32 "                \
        "{%0,%1,%2,%3}, {%4,%5,%6,%7}, {%8,%9}, {%0,%1,%2,%3};"               \
        : "+f"((dd)[0]), "+f"((dd)[1]), "+f"((dd)[2]), "+f"((dd)[3])          \
        : "r"((aa)[0]), "r"((aa)[1]), "r"((aa)[2]), "r"((aa)[3]),             \
          "r"(b0), "r"(b1))

#define LDSM4(f, a)                                                           \
    asm volatile("ldmatrix.sync.aligned.m8n8.x4.shared.b16 "                  \
                 "{%0,%1,%2,%3}, [%4];"                                       \
                 : "=r"((f)[0]), "=r"((f)[1]), "=r"((f)[2]), "=r"((f)[3])     \
                 : "r"(a))

// permuted A-row index for (gate G, unit u)
static __device__ __forceinline__ int prow(int G, int u) {
    return ((u >> 3) << 5) | ((G >> 1) << 4) | ((G & 1) << 3) | (u & 7);
}

static __device__ __forceinline__ uint32_t h2u(float a, float b) {
    __half2 h = __floats2half2_rn(a, b);
    return *reinterpret_cast<uint32_t*>(&h);
}

// pack pre-activation accumulators -> thread-private scratch (fp16 pairs)
static __device__ __forceinline__ void packdd(uint32_t* sc, float dd[2][7][4]) {
#pragma unroll
    for (int p = 0; p < 7; p++) {
        sc[p * 4 + 0] = h2u(dd[0][p][0], dd[0][p][1]);   // i pre (c0,c1)
        sc[p * 4 + 1] = h2u(dd[0][p][2], dd[0][p][3]);   // f
        sc[p * 4 + 2] = h2u(dd[1][p][0], dd[1][p][1]);   // g
        sc[p * 4 + 3] = h2u(dd[1][p][2], dd[1][p][3]);   // o
    }
}

// one seq-pair LSTM cell from scratch pre-acts; writes h (bf16) + opt fp32
static __device__ __forceinline__ void cellp(const uint32_t* sc, int p,
                                             const float* bg, float* cst,
                                             __nv_bfloat16* htw, int pitch,
                                             int un, int tq, float* h1fp) {
    __half2 I2 = *(const __half2*)(sc + p * 4 + 0);
    __half2 F2 = *(const __half2*)(sc + p * 4 + 1);
    __half2 G2 = *(const __half2*)(sc + p * 4 + 2);
    __half2 O2 = *(const __half2*)(sc + p * 4 + 3);
    float vi[2] = {__low2float(I2), __high2float(I2)};
    float vf[2] = {__low2float(F2), __high2float(F2)};
    float vg[2] = {__low2float(G2), __high2float(G2)};
    float vo[2] = {__low2float(O2), __high2float(O2)};
#pragma unroll
    for (int c = 0; c < 2; c++) {
        float I = sigm_(vi[c] + bg[0]);
        float F = sigm_(vf[c] + bg[1]);
        float G = tanh_(vg[c] + bg[2]);
        float O = sigm_(vo[c] + bg[3]);
        float cc = fmaf(F, cst[p * 2 + c], I * G);
        cst[p * 2 + c] = cc;
        float h = O * tanh_(cc);
        int n = p * 8 + tq * 2 + c;
        htw[n * pitch + un] = __float2bfloat16(h);
        if (h1fp) h1fp[n * 66 + un] = h;
    }
}

static __device__ __forceinline__ void ldx(const float* __restrict__ hist,
                                           const float* __restrict__ fut,
                                           int myb, int myn, int t,
                                           float& x0, float& x1, float& x2,
                                           float& x3, float& x4) {
    const float* s1 = (t < 336)
        ? hist + (((size_t)myb * 336 + t) * 512 + myn) * 5
        : fut  + (((size_t)myb * 48 + (t - 336)) * 512 + myn) * 5;
    int tc = t + 1;
    const float* s2 = (tc < 336)
        ? hist + (((size_t)myb * 336 + tc) * 512 + myn) * 5
        : fut  + (((size_t)myb * 48 + (tc - 336)) * 512 + myn) * 5;
    x0 = s1[0];
    x1 = s2[1]; x2 = s2[2]; x3 = s2[3]; x4 = s2[4];
}

extern "C" __global__ void __launch_bounds__(TPB, 1)
deepar_kernel(const float* __restrict__ hist, const float* __restrict__ fut,
              const float* __restrict__ emb_W, const float* __restrict__ emb_b,
              const float* __restrict__ W_ih0, const float* __restrict__ W_hh0,
              const float* __restrict__ b_ih0, const float* __restrict__ b_hh0,
              const float* __restrict__ W_ih1, const float* __restrict__ W_hh1,
              const float* __restrict__ b_ih1, const float* __restrict__ b_hh1,
              const float* __restrict__ head_W, const float* __restrict__ head_b,
              float* __restrict__ out)
{
    extern __shared__ char sm[];
    const int tid = threadIdx.x;
    const int wid = tid >> 5, lane = tid & 31;
    const int gid = lane >> 2, tq = lane & 3;
    const int mbase = wid * 32;
    const int un = (wid << 3) + gid;        // this thread's hidden unit

    const bool duty = (tid < SEQ);
    const int mys = duty ? tid : 0;
    const int gbase = blockIdx.x * SEQ;
    int mygs = gbase + mys; if (mygs > NSEQ_TOT - 1) mygs = NSEQ_TOT - 1;
    const int myb = mygs >> 9, myn = mygs & 511;

    // ---- zero weights pads + hT bufs ----
    for (int e = tid; e < 159744 / 4; e += TPB) ((uint32_t*)sm)[e] = 0;
    __syncthreads();

    // ---- weights, permuted rows ----
    __nv_bfloat16* w0  = (__nv_bfloat16*)(sm + OB_W0);
    __nv_bfloat16* wi1 = (__nv_bfloat16*)(sm + OB_WI1);
    __nv_bfloat16* wh1 = (__nv_bfloat16*)(sm + OB_WH1);
    for (int e = tid; e < 256 * 64; e += TPB) {
        int r = e >> 6, k = e & 63;
        int p = prow(r >> 6, r & 63);
        w0[p * PW0 + k]  = __float2bfloat16(W_hh0[e]);
        wi1[p * PW1 + k] = __float2bfloat16(W_ih1[e]);
        wh1[p * PW1 + k] = __float2bfloat16(W_hh1[e]);
    }
    {   // x-projection columns of L0 A-tile: k=64 -> v1, 65..68 -> wc
        int r = tid;
        int p = prow(r >> 6, r & 63);
        const float* wr = W_ih0 + r * 36;
        float a = 0.f;
#pragma unroll
        for (int e = 0; e < 32; e++) a = fmaf(wr[e], emb_W[e], a);
        w0[p * PW0 + 64] = __float2bfloat16(a);
#pragma unroll
        for (int k = 0; k < 4; k++)
            w0[p * PW0 + 65 + k] = __float2bfloat16(wr[32 + k]);
    }
    if (tid < 128) ((float*)(sm + OB_HW))[tid] = head_W[tid];
    if (tid < 2)   ((float*)(sm + OB_HB))[tid] = head_b[tid];

    // ---- per-thread fp32 gate biases for unit un ----
    float v2g[4], b1g[4];
#pragma unroll
    for (int G = 0; G < 4; G++) {
        int r = G * 64 + un;
        const float* wr = W_ih0 + r * 36;
        float bb = 0.f;
#pragma unroll
        for (int e = 0; e < 32; e++) bb = fmaf(wr[e], emb_b[e], bb);
        v2g[G] = bb + b_ih0[r] + b_hh0[r];
        b1g[G] = b_ih1[r] + b_hh1[r];
    }

    float c0[14], c1[14];
#pragma unroll
    for (int i = 0; i < 14; i++) { c0[i] = 0.f; c1[i] = 0.f; }

    // stage x(0) into hT0 buf0 (k=64..68)
    if (duty) {
        float a0, a1, a2, a3, a4;
        ldx(hist, fut, myb, myn, 0, a0, a1, a2, a3, a4);
        __nv_bfloat16* xb = (__nv_bfloat16*)(sm + OB_HT0);
        xb[mys * PH0 + 64] = __float2bfloat16(a0);
        xb[mys * PH0 + 65] = __float2bfloat16(a1);
        xb[mys * PH0 + 66] = __float2bfloat16(a2);
        xb[mys * PH0 + 67] = __float2bfloat16(a3);
        xb[mys * PH0 + 68] = __float2bfloat16(a4);
    }
    __syncthreads();

    const uint32_t aoff0 =
        (uint32_t)(((mbase + (lane & 15)) * PW0 + ((lane >> 4) << 3)) * 2);
    const uint32_t aoff1 =
        (uint32_t)(((mbase + (lane & 15)) * PW1 + ((lane >> 4) << 3)) * 2);
    const uint32_t uW0 = s2u(sm + OB_W0) + aoff0;
    const uint32_t uWI = s2u(sm + OB_WI1) + aoff1;
    const uint32_t uWH = s2u(sm + OB_WH1) + aoff1;
    uint32_t* sc = (uint32_t*)(sm + OB_SC) + tid * 29;

    for (int t = 0; t < NSTEP; t++) {
        const int rd = t & 1, wr = rd ^ 1;
        const char* ht0r = sm + OB_HT0 + rd * HT0_SZ;
        char*       ht0w = sm + OB_HT0 + wr * HT0_SZ;
        char*       ht1c = sm + OB_HT1 + rd * HT1_SZ;   // h1(t-1) buf
        float*      h1fc = (float*)(sm + OB_H1F + rd * H1F_SZ);

        const bool pf = duty && (t + 1 < NSTEP);
        float xr0, xr1, xr2, xr3, xr4;
        if (pf) ldx(hist, fut, myb, myn, t + 1, xr0, xr1, xr2, xr3, xr4);

        float dd[2][7][4];
#pragma unroll
        for (int mt = 0; mt < 2; mt++)
#pragma unroll
            for (int nt = 0; nt < 7; nt++)
#pragma unroll
                for (int q = 0; q < 4; q++) dd[mt][nt][q] = 0.f;

        // ===== phase1: MMA0 (Whh0|x) || cellL1(t-1) =====
        float* h1w = (t >= 336) ? h1fc : (float*)0;
#pragma unroll
        for (int kt = 0; kt < 5; kt++) {
            uint32_t f0[4], f1[4];
            LDSM4(f0, uW0 + kt * 32);
            LDSM4(f1, uW0 + 16 * PW0 * 2 + kt * 32);
#pragma unroll
            for (int nt = 0; nt < 7; nt++) {
                const char* bp = ht0r
                    + ((nt * 8 + gid) * PH0 + kt * 16 + tq * 2) * 2;
                uint32_t b0 = *(const uint32_t*)bp;
                uint32_t b1 = *(const uint32_t*)(bp + 16);
                MMA(dd[0][nt], f0, b0, b1);
                MMA(dd[1][nt], f1, b0, b1);
            }
            if (t > 0) {     // cellL1(t-1): pairs (2,2,2,1,0) per kt
                if (kt < 3) {
                    cellp(sc, kt * 2, b1g, c1, (__nv_bfloat16*)ht1c, PH1,
                          un, tq, h1w);
                    cellp(sc, kt * 2 + 1, b1g, c1, (__nv_bfloat16*)ht1c, PH1,
                          un, tq, h1w);
                } else if (kt == 3) {
                    cellp(sc, 6, b1g, c1, (__nv_bfloat16*)ht1c, PH1,
                          un, tq, h1w);
                }
            }
        }
        packdd(sc, dd);              // scratch := pre0(t)
        __syncthreads();   // bar1: h1(t-1), h1f visible

        // ===== phase2a: MMA1b (Whh1 @ h1(t-1)) || cellL0(t) =====
#pragma unroll
        for (int mt = 0; mt < 2; mt++)
#pragma unroll
            for (int nt = 0; nt < 7; nt++)
#pragma unroll
                for (int q = 0; q < 4; q++) dd[mt][nt][q] = 0.f;
#pragma unroll
        for (int kt = 0; kt < 4; kt++) {
            uint32_t f0[4], f1[4];
            LDSM4(f0, uWH + kt * 32);
            LDSM4(f1, uWH + 16 * PW1 * 2 + kt * 32);
#pragma unroll
            for (int nt = 0; nt < 7; nt++) {
                const char* bp = ht1c
                    + ((nt * 8 + gid) * PH1 + kt * 16 + tq * 2) * 2;
                uint32_t b0 = *(const uint32_t*)bp;
                uint32_t b1 = *(const uint32_t*)(bp + 16);
                MMA(dd[0][nt], f0, b0, b1);
                MMA(dd[1][nt], f1, b0, b1);
            }
            // cellL0(t): pairs (2,2,2,1) per kt
            if (kt < 3) {
                cellp(sc, kt * 2, v2g, c0, (__nv_bfloat16*)ht0w, PH0,
                      un, tq, (float*)0);
                cellp(sc, kt * 2 + 1, v2g, c0, (__nv_bfloat16*)ht0w, PH0,
                      un, tq, (float*)0);
            } else {
                cellp(sc, 6, v2g, c0, (__nv_bfloat16*)ht0w, PH0,
                      un, tq, (float*)0);
            }
        }
        // stage x(t+1) into ht0w k=64..68
        if (pf) {
            __nv_bfloat16* xb = (__nv_bfloat16*)ht0w;
            xb[mys * PH0 + 64] = __float2bfloat16(xr0);
            xb[mys * PH0 + 65] = __float2bfloat16(xr1);
            xb[mys * PH0 + 66] = __float2bfloat16(xr2);
            xb[mys * PH0 + 67] = __float2bfloat16(xr3);
            xb[mys * PH0 + 68] = __float2bfloat16(xr4);
        }
        // head(t-1)
        if (t >= 336 && duty) {
            const float* hr = h1fc + mys * 66;
            const float* hwp = (const float*)(sm + OB_HW);
            float p0 = ((const float*)(sm + OB_HB))[0];
            float p1 = ((const float*)(sm + OB_HB))[1];
#pragma unroll 8
            for (int j = 0; j < 64; j++) {
                float v = fmaxf(hr[j], 0.f);
                p0 = fmaf(v, hwp[j], p0);
                p1 = fmaf(v, hwp[64 + j], p1);
            }
            float sp = (p1 > 15.f) ? p1 : log1pf(__expf(p1));
            ((float2*)out)[((size_t)myb * 48 + (t - 336)) * 512 + myn] =
                make_float2(p0, sp);
        }
        __syncthreads();   // bar2: h0(t), x(t+1) visible

        // ===== phase2b: dd += Wih1 @ h0(t); pack pre1(t) =====
#pragma unroll
        for (int kt = 0; kt < 4; kt++) {
            uint32_t f0[4], f1[4];
            LDSM4(f0, uWI + kt * 32);
            LDSM4(f1, uWI + 16 * PW1 * 2 + kt * 32);
#pragma unroll
            for (int nt = 0; nt < 7; nt++) {
                const char* bp = ht0w
                    + ((nt * 8 + gid) * PH0 + kt * 16 + tq * 2) * 2;
                uint32_t b0 = *(const uint32_t*)bp;
                uint32_t b1 = *(const uint32_t*)(bp + 16);
                MMA(dd[0][nt], f0, b0, b1);
                MMA(dd[1][nt], f1, b0, b1);
            }
        }
        packdd(sc, dd);              // scratch := pre1(t)
        // no barrier: next phase1 deps all bar-separated (double buffers)
    }

    // ---- drain: cellL1(382) -> h1f buf0; head(382) ----
    {
        float* h1fd = (float*)(sm + OB_H1F);
#pragma unroll
        for (int p = 0; p < 7; p++)
            cellp(sc, p, b1g, c1, (__nv_bfloat16*)(sm + OB_HT1), PH1,
                  un, tq, h1fd);
    }
    __syncthreads();
    if (duty) {
        const float* hr = (const float*)(sm + OB_H1F) + mys * 66;
        const float* hwp = (const float*)(sm + OB_HW);
        float p0 = ((const float*)(sm + OB_HB))[0];
        float p1 = ((const float*)(sm + OB_HB))[1];
#pragma unroll 8
        for (int j = 0; j < 64; j++) {
            float v = fmaxf(hr[j], 0.f);
            p0 = fmaf(v, hwp[j], p0);
            p1 = fmaf(v, hwp[64 + j], p1);
        }
        float sp = (p1 > 15.f) ? p1 : log1pf(__expf(p1));
        ((float2*)out)[((size_t)myb * 48 + 47) * 512 + myn] = make_float2(p0, sp);
    }
}

extern "C" void kernel_launch(void* const* d_in, const int* in_sizes, int n_in,
                              void* d_out, int out_size) {
    (void)in_sizes; (void)n_in; (void)out_size;
    cudaFuncSetAttribute(deepar_kernel,
                         cudaFuncAttributeMaxDynamicSharedMemorySize, SM_BYTES);
    deepar_kernel<<<NCTA, TPB, SM_BYTES>>>(
        (const float*)d_in[0], (const float*)d_in[1],
        (const float*)d_in[2], (const float*)d_in[3],
        (const float*)d_in[4], (const float*)d_in[5],
        (const float*)d_in[6], (const float*)d_in[7],
        (const float*)d_in[8], (const float*)d_in[9],
        (const float*)d_in[10], (const float*)d_in[11],
        (const float*)d_in[12], (const float*)d_in[13],
        (float*)d_out);
}